// round 15
// baseline (speedup 1.0000x reference)
#include <cuda_runtime.h>
#include <cstdint>

// QLinear with TRUE sequential bf16 accumulation (bit-exact vs reference):
//   acc = bf16(acc + bf16(x_k * w_k)) for k = 0..4095, then + bias (bf16 add).
// Tensors are fp32 containers of bf16 values: load fp32, use hi 16 bits,
// run the trajectory with mul.rn.bf16x2/add.rn.bf16x2 inline asm (no FMA
// contraction possible), store fp32 via <<16.
//
// R15: occupancy 3 (24 warps/SM) to close the fma-eligibility gap seen at
// occ 2 (fma=87.5%). Prefetch split into x-batch / w-batch so peak prefetch
// register pressure is 16 (target <=84 regs for 3 CTAs/SM).

#define IN_F   4096
#define OUT_F  4096
#define N_ROWS 8192

static constexpr int KC      = 32;
static constexpr int NCHUNK  = IN_F / KC;     // 128
static constexpr int RT      = 128;
static constexpr int CT      = 128;
static constexpr int THREADS = 256;
static constexpr int XSTR    = 132;           // u32 per k-slice (x, splatted)
static constexpr int WSTR    = 136;           // u16 per k-slice (w)

__device__ __forceinline__ unsigned bf2_mul(unsigned a, unsigned b) {
    unsigned d;
    asm("mul.rn.bf16x2 %0, %1, %2;" : "=r"(d) : "r"(a), "r"(b));
    return d;
}
__device__ __forceinline__ unsigned bf2_add(unsigned a, unsigned b) {
    unsigned d;
    asm("add.rn.bf16x2 %0, %1, %2;" : "=r"(d) : "r"(a), "r"(b));
    return d;
}

// compute 'CNT' consecutive k-slices starting at kk0 from buffer (xb, wb)
#define KK_BLOCK(kk0, CNT)                                                        \
    _Pragma("unroll")                                                             \
    for (int kk = (kk0); kk < (kk0) + (CNT); kk++) {                              \
        uint4 a0 = *reinterpret_cast<const uint4*>(xb + kk * XSTR + rowgrp * 8);  \
        uint4 a1 = *reinterpret_cast<const uint4*>(xb + kk * XSTR + rowgrp * 8 + 4);\
        uint4 wv = *reinterpret_cast<const uint4*>(wb + kk * WSTR + jpgrp * 8);   \
        const unsigned xsp[8] = {a0.x, a0.y, a0.z, a0.w, a1.x, a1.y, a1.z, a1.w}; \
        const unsigned wpp[4] = {wv.x, wv.y, wv.z, wv.w};                         \
        _Pragma("unroll")                                                         \
        for (int r = 0; r < 8; r++)                                               \
            _Pragma("unroll")                                                     \
            for (int p = 0; p < 4; p++)                                           \
                acc[r][p] = bf2_add(acc[r][p], bf2_mul(xsp[r], wpp[p]));          \
    }

__global__ __launch_bounds__(THREADS, 3)
void qlinear_seqbf16_kernel(const float* __restrict__ x,
                            const float* __restrict__ w,
                            const float* __restrict__ bias,
                            float* __restrict__ out)
{
    __shared__ __align__(16) unsigned       xs[2][KC * XSTR];  // 33792 B
    __shared__ __align__(16) unsigned short ws[2][KC * WSTR];  // 17408 B

    const int t      = threadIdx.x;
    const int rowgrp = t >> 4;
    const int jpgrp  = t & 15;
    const int n0     = blockIdx.y * RT;
    const int j0     = blockIdx.x * CT;

    const int srow = t >> 3;              // 0..31
    const int sk4  = t & 7;               // 0..7

    // per-thread base pointers for staging (4 row-slabs)
    const float* xg = x + (size_t)(n0 + srow) * IN_F + sk4 * 4;
    const float* wg = w + (size_t)(j0 + srow) * IN_F + sk4 * 4;
    const size_t slab = (size_t)32 * IN_F;

    unsigned acc[8][4];
    #pragma unroll
    for (int r = 0; r < 8; r++)
        #pragma unroll
        for (int p = 0; p < 4; p++)
            acc[r][p] = 0u;

    // ---- prologue: stage chunk 0 into buffer 0 ----
    #pragma unroll
    for (int i = 0; i < 4; i++) {
        float4 xf = *reinterpret_cast<const float4*>(xg + i * slab);
        float4 wf = *reinterpret_cast<const float4*>(wg + i * slab);
        const unsigned* xu = reinterpret_cast<const unsigned*>(&xf);
        const unsigned* wu = reinterpret_cast<const unsigned*>(&wf);
        const int row = i * 32 + srow;
        #pragma unroll
        for (int s = 0; s < 4; s++) {
            xs[0][(sk4 * 4 + s) * XSTR + row] = __byte_perm(xu[s], xu[s], 0x3232);
            ws[0][(sk4 * 4 + s) * WSTR + row] = (unsigned short)(wu[s] >> 16);
        }
    }
    __syncthreads();

    // ---- main pipelined loop ----
    #pragma unroll 1
    for (int c = 0; c < NCHUNK - 1; c++) {
        const int pb  = c & 1;
        const int kcn = (c + 1) * KC;
        const unsigned*       xb = &xs[pb][0];
        const unsigned short* wb = &ws[pb][0];
        unsigned*       xd = &xs[pb ^ 1][0];
        unsigned short* wd = &ws[pb ^ 1][0];

        // prefetch x of next chunk (16 regs live)
        float4 xf[4];
        #pragma unroll
        for (int i = 0; i < 4; i++)
            xf[i] = *reinterpret_cast<const float4*>(xg + kcn + i * slab);

        KK_BLOCK(0, 4)

        #pragma unroll
        for (int i = 0; i < 4; i++) {
            const unsigned* xu = reinterpret_cast<const unsigned*>(&xf[i]);
            const int row = i * 32 + srow;
            #pragma unroll
            for (int s = 0; s < 4; s++)
                xd[(sk4 * 4 + s) * XSTR + row] = __byte_perm(xu[s], xu[s], 0x3232);
        }

        // prefetch w of next chunk (16 regs live)
        float4 wf[4];
        #pragma unroll
        for (int i = 0; i < 4; i++)
            wf[i] = *reinterpret_cast<const float4*>(wg + kcn + i * slab);

        KK_BLOCK(4, 4)

        #pragma unroll
        for (int i = 0; i < 4; i++) {
            const unsigned* wu = reinterpret_cast<const unsigned*>(&wf[i]);
            const int row = i * 32 + srow;
            #pragma unroll
            for (int s = 0; s < 4; s++)
                wd[(sk4 * 4 + s) * WSTR + row] = (unsigned short)(wu[s] >> 16);
        }

        KK_BLOCK(8, 24)

        __syncthreads();
    }

    // ---- final chunk: no prefetch ----
    {
        const unsigned*       xb = &xs[(NCHUNK - 1) & 1][0];
        const unsigned short* wb = &ws[(NCHUNK - 1) & 1][0];
        KK_BLOCK(0, 32)
    }

    // ---- bias (bf16 add, per reference) ----
    unsigned bp[4];
    #pragma unroll
    for (int p = 0; p < 4; p++) {
        unsigned b0 = __float_as_uint(bias[j0 + jpgrp * 8 + 2 * p]);
        unsigned b1 = __float_as_uint(bias[j0 + jpgrp * 8 + 2 * p + 1]);
        bp[p] = __byte_perm(b0, b1, 0x7632);
    }
    #pragma unroll
    for (int r = 0; r < 8; r++)
        #pragma unroll
        for (int p = 0; p < 4; p++)
            acc[r][p] = bf2_add(acc[r][p], bp[p]);

    // ---- store fp32 (bf16 bits << 16), 2x STG.128 per row ----
    #pragma unroll
    for (int r = 0; r < 8; r++) {
        const size_t obase = (size_t)(n0 + rowgrp * 8 + r) * OUT_F + j0 + jpgrp * 8;
        uint4 o1, o2;
        o1.x = acc[r][0] << 16;  o1.y = acc[r][0] & 0xFFFF0000u;
        o1.z = acc[r][1] << 16;  o1.w = acc[r][1] & 0xFFFF0000u;
        o2.x = acc[r][2] << 16;  o2.y = acc[r][2] & 0xFFFF0000u;
        o2.z = acc[r][3] << 16;  o2.w = acc[r][3] & 0xFFFF0000u;
        *reinterpret_cast<uint4*>(out + obase)     = o1;
        *reinterpret_cast<uint4*>(out + obase + 4) = o2;
    }
}

extern "C" void kernel_launch(void* const* d_in, const int* in_sizes, int n_in,
                              void* d_out, int out_size)
{
    (void)out_size;
    const float* x = nullptr;
    const float* w = nullptr;
    const float* b = nullptr;
    for (int i = 0; i < n_in; i++) {
        if      (in_sizes[i] == N_ROWS * IN_F) x = (const float*)d_in[i];
        else if (in_sizes[i] == OUT_F * IN_F)  w = (const float*)d_in[i];
        else if (in_sizes[i] == OUT_F)         b = (const float*)d_in[i];
    }
    if (!x || !w || !b) {
        int a0 = 0, a1 = 1, a2 = 2;
        if (in_sizes[a0] < in_sizes[a1]) { int tmp = a0; a0 = a1; a1 = tmp; }
        if (in_sizes[a1] < in_sizes[a2]) { int tmp = a1; a1 = a2; a2 = tmp; }
        if (in_sizes[a0] < in_sizes[a1]) { int tmp = a0; a0 = a1; a1 = tmp; }
        x = (const float*)d_in[a0];
        w = (const float*)d_in[a1];
        b = (const float*)d_in[a2];
    }
    float* out = (float*)d_out;

    dim3 grid(OUT_F / CT, N_ROWS / RT);   // (32, 64)
    qlinear_seqbf16_kernel<<<grid, THREADS>>>(x, w, b, out);
}

// round 16
// speedup vs baseline: 1.0466x; 1.0466x over previous
#include <cuda_runtime.h>
#include <cstdint>

// QLinear with TRUE sequential bf16 accumulation (bit-exact vs reference):
//   acc = bf16(acc + bf16(x_k * w_k)) for k = 0..4095, then + bias (bf16 add).
// Tensors are fp32 containers of bf16 values: load fp32, use hi 16 bits,
// run the trajectory with mul.rn.bf16x2/add.rn.bf16x2 inline asm (no FMA
// contraction possible), store fp32 via <<16.
//
// R16: 3-stage smem ring with a MID-CHUNK barrier. Ring gives the only
// barrier per chunk ~24 k-steps of post-barrier compute slack per warp, so
// rendezvous stalls are absorbed. x stored as u16 (PRMT splat in-loop, rides
// the idle alu pipe) so 3 stages fit 52KB/CTA -> occupancy 3 with margin.

#define IN_F   4096
#define OUT_F  4096
#define N_ROWS 8192

static constexpr int KC      = 32;
static constexpr int NCHUNK  = IN_F / KC;     // 128
static constexpr int RT      = 128;
static constexpr int CT      = 128;
static constexpr int THREADS = 256;
static constexpr int STR     = 136;           // u16 per k-slice; 272B = 16B-multiple

__device__ __forceinline__ unsigned bf2_mul(unsigned a, unsigned b) {
    unsigned d;
    asm("mul.rn.bf16x2 %0, %1, %2;" : "=r"(d) : "r"(a), "r"(b));
    return d;
}
__device__ __forceinline__ unsigned bf2_add(unsigned a, unsigned b) {
    unsigned d;
    asm("add.rn.bf16x2 %0, %1, %2;" : "=r"(d) : "r"(a), "r"(b));
    return d;
}

// compute CNT consecutive k-slices starting at kk0 from buffers (xb, wb)
#define KK_BLOCK(kk0, CNT)                                                          \
    _Pragma("unroll")                                                               \
    for (int kk = (kk0); kk < (kk0) + (CNT); kk++) {                                \
        uint4 xv4 = *reinterpret_cast<const uint4*>(xb + kk * STR + rowgrp * 8);    \
        uint4 wv4 = *reinterpret_cast<const uint4*>(wb + kk * STR + jpgrp * 8);     \
        const unsigned xw[4]  = {xv4.x, xv4.y, xv4.z, xv4.w};                       \
        const unsigned wpp[4] = {wv4.x, wv4.y, wv4.z, wv4.w};                       \
        _Pragma("unroll")                                                           \
        for (int r = 0; r < 8; r++) {                                               \
            unsigned xsp = __byte_perm(xw[r >> 1], 0, (r & 1) ? 0x3232 : 0x1010);   \
            _Pragma("unroll")                                                       \
            for (int p = 0; p < 4; p++)                                             \
                acc[r][p] = bf2_add(acc[r][p], bf2_mul(xsp, wpp[p]));               \
        }                                                                           \
    }

__global__ __launch_bounds__(THREADS, 3)
void qlinear_seqbf16_kernel(const float* __restrict__ x,
                            const float* __restrict__ w,
                            const float* __restrict__ bias,
                            float* __restrict__ out)
{
    // 3-stage ring: bf16 bits, [stage][k][row/col]
    __shared__ __align__(16) unsigned short xs[3][KC * STR];  // 3*8704 B
    __shared__ __align__(16) unsigned short ws[3][KC * STR];  // 3*8704 B

    const int t      = threadIdx.x;
    const int rowgrp = t >> 4;            // 0..15 -> rows rowgrp*8..+7
    const int jpgrp  = t & 15;            // 0..15 -> cols jpgrp*8..+7
    const int n0     = blockIdx.y * RT;
    const int j0     = blockIdx.x * CT;

    const int srow = t >> 3;              // 0..31
    const int sk4  = t & 7;               // 0..7

    const float* xg = x + (size_t)(n0 + srow) * IN_F + sk4 * 4;
    const float* wg = w + (size_t)(j0 + srow) * IN_F + sk4 * 4;
    const size_t slab = (size_t)32 * IN_F;

    unsigned acc[8][4];
    #pragma unroll
    for (int r = 0; r < 8; r++)
        #pragma unroll
        for (int p = 0; p < 4; p++)
            acc[r][p] = 0u;

    // ---- prologue: stage chunk 0 into stage 0 ----
    #pragma unroll
    for (int i = 0; i < 4; i++) {
        float4 xf = *reinterpret_cast<const float4*>(xg + i * slab);
        float4 wf = *reinterpret_cast<const float4*>(wg + i * slab);
        const unsigned* xu = reinterpret_cast<const unsigned*>(&xf);
        const unsigned* wu = reinterpret_cast<const unsigned*>(&wf);
        const int row = i * 32 + srow;
        #pragma unroll
        for (int s = 0; s < 4; s++) {
            xs[0][(sk4 * 4 + s) * STR + row] = (unsigned short)(xu[s] >> 16);
            ws[0][(sk4 * 4 + s) * STR + row] = (unsigned short)(wu[s] >> 16);
        }
    }
    __syncthreads();

    // ---- main loop: chunk c reads stage c%3, stages c+1 into (c+1)%3 ----
    // Single barrier per chunk, placed right after STS: KK(8..31) is slack.
    // Safety: writes to stage s=(c+1)%3 become visible across the barrier
    // before chunk c+1's first read; the last reads of stage s happened in
    // chunk c-2, separated from these writes by chunk c-1's barrier.
    #pragma unroll 1
    for (int c = 0; c < NCHUNK - 1; c++) {
        const unsigned short* xb = &xs[c % 3][0];
        const unsigned short* wb = &ws[c % 3][0];
        unsigned short* xd = &xs[(c + 1) % 3][0];
        unsigned short* wd = &ws[(c + 1) % 3][0];
        const int kcn = (c + 1) * KC;

        // prefetch x of next chunk (16 regs live)
        float4 xf[4];
        #pragma unroll
        for (int i = 0; i < 4; i++)
            xf[i] = *reinterpret_cast<const float4*>(xg + kcn + i * slab);

        KK_BLOCK(0, 4)

        #pragma unroll
        for (int i = 0; i < 4; i++) {
            const unsigned* xu = reinterpret_cast<const unsigned*>(&xf[i]);
            const int row = i * 32 + srow;
            #pragma unroll
            for (int s = 0; s < 4; s++)
                xd[(sk4 * 4 + s) * STR + row] = (unsigned short)(xu[s] >> 16);
        }

        // prefetch w of next chunk (16 regs live)
        float4 wf[4];
        #pragma unroll
        for (int i = 0; i < 4; i++)
            wf[i] = *reinterpret_cast<const float4*>(wg + kcn + i * slab);

        KK_BLOCK(4, 4)

        #pragma unroll
        for (int i = 0; i < 4; i++) {
            const unsigned* wu = reinterpret_cast<const unsigned*>(&wf[i]);
            const int row = i * 32 + srow;
            #pragma unroll
            for (int s = 0; s < 4; s++)
                wd[(sk4 * 4 + s) * STR + row] = (unsigned short)(wu[s] >> 16);
        }

        __syncthreads();   // the ONLY barrier; KK(8..31) below is its slack

        KK_BLOCK(8, 24)
    }

    // ---- final chunk: compute only ----
    {
        const unsigned short* xb = &xs[(NCHUNK - 1) % 3][0];
        const unsigned short* wb = &ws[(NCHUNK - 1) % 3][0];
        KK_BLOCK(0, 32)
    }

    // ---- bias (bf16 add, per reference) ----
    unsigned bp[4];
    #pragma unroll
    for (int p = 0; p < 4; p++) {
        unsigned b0 = __float_as_uint(bias[j0 + jpgrp * 8 + 2 * p]);
        unsigned b1 = __float_as_uint(bias[j0 + jpgrp * 8 + 2 * p + 1]);
        bp[p] = __byte_perm(b0, b1, 0x7632);
    }
    #pragma unroll
    for (int r = 0; r < 8; r++)
        #pragma unroll
        for (int p = 0; p < 4; p++)
            acc[r][p] = bf2_add(acc[r][p], bp[p]);

    // ---- store fp32 (bf16 bits << 16), 2x STG.128 per row ----
    #pragma unroll
    for (int r = 0; r < 8; r++) {
        const size_t obase = (size_t)(n0 + rowgrp * 8 + r) * OUT_F + j0 + jpgrp * 8;
        uint4 o1, o2;
        o1.x = acc[r][0] << 16;  o1.y = acc[r][0] & 0xFFFF0000u;
        o1.z = acc[r][1] << 16;  o1.w = acc[r][1] & 0xFFFF0000u;
        o2.x = acc[r][2] << 16;  o2.y = acc[r][2] & 0xFFFF0000u;
        o2.z = acc[r][3] << 16;  o2.w = acc[r][3] & 0xFFFF0000u;
        *reinterpret_cast<uint4*>(out + obase)     = o1;
        *reinterpret_cast<uint4*>(out + obase + 4) = o2;
    }
}

extern "C" void kernel_launch(void* const* d_in, const int* in_sizes, int n_in,
                              void* d_out, int out_size)
{
    (void)out_size;
    const float* x = nullptr;
    const float* w = nullptr;
    const float* b = nullptr;
    for (int i = 0; i < n_in; i++) {
        if      (in_sizes[i] == N_ROWS * IN_F) x = (const float*)d_in[i];
        else if (in_sizes[i] == OUT_F * IN_F)  w = (const float*)d_in[i];
        else if (in_sizes[i] == OUT_F)         b = (const float*)d_in[i];
    }
    if (!x || !w || !b) {
        int a0 = 0, a1 = 1, a2 = 2;
        if (in_sizes[a0] < in_sizes[a1]) { int tmp = a0; a0 = a1; a1 = tmp; }
        if (in_sizes[a1] < in_sizes[a2]) { int tmp = a1; a1 = a2; a2 = tmp; }
        if (in_sizes[a0] < in_sizes[a1]) { int tmp = a0; a0 = a1; a1 = tmp; }
        x = (const float*)d_in[a0];
        w = (const float*)d_in[a1];
        b = (const float*)d_in[a2];
    }
    float* out = (float*)d_out;

    dim3 grid(OUT_F / CT, N_ROWS / RT);   // (32, 64)
    qlinear_seqbf16_kernel<<<grid, THREADS>>>(x, w, b, out);
}